// round 12
// baseline (speedup 1.0000x reference)
#include <cuda_runtime.h>
#include <cstdint>

// TitansMemory B=16 L=8192 DK=DV=128 — direct recurrence v6b "pipelined fold",
// bugfix of R11: step-(i+1) raw dots are computed vs PRE-update state (before
// step i's W/m update), so the r_i correction applied at i+1 is exact and the
// fold is independent of r_i (overlaps with the scalar chain).
//   correction: wk_i = x + cS*t + cA*r*G[i-1] ; mk_i = t + cB*r*G[i-1]
//               (q-classes use H[i-1]); r_i = cCP*wk_i - v_i.
// 1 row/warp, 128 CTAs x 512 thr; k/q/v double-buffered via cp.async.

#define CSTEPS 16
#define L_SEQ  8192
#define NCH    (L_SEQ / CSTEPS)
#define DK     128

using ull = unsigned long long;

__device__ __forceinline__ ull pk(float lo, float hi) {
    ull r; asm("mov.b64 %0,{%1,%2};" : "=l"(r) : "f"(lo), "f"(hi)); return r;
}
__device__ __forceinline__ float hadd2(ull p) {
    float lo, hi; asm("mov.b64 {%0,%1},%2;" : "=f"(lo), "=f"(hi) : "l"(p));
    return lo + hi;
}
__device__ __forceinline__ ull mul2(ull a, ull b) {
    ull d; asm("mul.rn.f32x2 %0,%1,%2;" : "=l"(d) : "l"(a), "l"(b)); return d;
}
__device__ __forceinline__ ull fma2(ull a, ull b, ull c) {
    ull d; asm("fma.rn.f32x2 %0,%1,%2,%3;" : "=l"(d) : "l"(a), "l"(b), "l"(c)); return d;
}
__device__ __forceinline__ unsigned su32(const void* p) {
    return (unsigned)__cvta_generic_to_shared(p);
}
__device__ __forceinline__ void cp16(unsigned s, const void* g) {
    asm volatile("cp.async.cg.shared.global [%0],[%1],16;" :: "r"(s), "l"(g));
}
__device__ __forceinline__ void cp4(unsigned s, const void* g) {
    asm volatile("cp.async.ca.shared.global [%0],[%1],4;" :: "r"(s), "l"(g));
}
__device__ __forceinline__ void cp_commit() {
    asm volatile("cp.async.commit_group;" ::: "memory");
}
__device__ __forceinline__ void cp_wait_all() {
    asm volatile("cp.async.wait_group 0;" ::: "memory");
}
__device__ __forceinline__ float dot4(float4 a, float4 b) {
    return fmaf(a.x, b.x, fmaf(a.y, b.y, fmaf(a.z, b.z, a.w * b.w)));
}

__global__ __launch_bounds__(512, 1)
void titans_kernel(const float* __restrict__ Q,
                   const float* __restrict__ K,
                   const float* __restrict__ V,
                   float* __restrict__ Y) {
    static constexpr float cCP[16] = {  // 0.98^i
        1.0f, 0.98f, 0.9604f, 0.941192f, 0.92236816f, 0.9039207968f,
        0.8858423809f, 0.8681255332f, 0.8507630226f, 0.8337477621f,
        0.8170728069f, 0.8007313508f, 0.7847167237f, 0.7690223892f,
        0.7536419414f, 0.7385691035f };
    static constexpr float cCY[16] = {  // 0.98^(i+1)
        0.98f, 0.9604f, 0.941192f, 0.92236816f, 0.9039207968f, 0.8858423809f,
        0.8681255332f, 0.8507630226f, 0.8337477621f, 0.8170728069f,
        0.8007313508f, 0.7847167237f, 0.7690223892f, 0.7536419414f,
        0.7385691035f, 0.7237977214f };
    static constexpr float cS[16] = {   // -0.1*(0.9/0.98)^(i+1)
        -0.09183673469f, -0.08433985839f, -0.07745414463f, -0.07113064017f,
        -0.06532344097f, -0.05999029968f, -0.05509252418f, -0.05059456302f,
        -0.04646378542f, -0.04267021926f, -0.03918632342f, -0.03598663375f,
        -0.03304811221f, -0.03034970510f, -0.02787207213f, -0.02559670445f };
    static constexpr float cA[16] = {   // -0.02/0.98^(i+1)
        -0.02040816327f, -0.02082465640f, -0.02124964939f, -0.02168331570f,
        -0.02212583235f, -0.02257738015f, -0.02303814301f, -0.02350830920f,
        -0.02398807061f, -0.02447762307f, -0.02497716640f, -0.02548690449f,
        -0.02600704540f, -0.02653780143f, -0.02707938921f, -0.02763202981f };
    static constexpr float cB[16] = {   // 0.2/0.9^(i+1)
        0.2222222222f, 0.2469135802f, 0.2743484225f, 0.3048315805f,
        0.3387017561f, 0.3763352846f, 0.4181503162f, 0.4646114624f,
        0.5162349582f, 0.5735943980f, 0.6373271089f, 0.7081412321f,
        0.7868235912f, 0.8742484347f, 0.9713871497f, 1.0793190552f };
    constexpr float C16F = 0.7237977214f;   // 0.98^16
    constexpr float B16F = 0.1853020189f;   // 0.9^16

    __shared__ float kb[2][CSTEPS][DK];
    __shared__ float qb[2][CSTEPS][DK];
    __shared__ float vT[2][16][20];          // [row][step]
    __shared__ float yb[2][CSTEPS][16];      // [step][row]
    __shared__ float skqs[16];               // k_t.q_t
    __shared__ float Gs[16];                 // k_j.k_{j+1}, j<15
    __shared__ float Hs[16];                 // k_j.q_{j+1}, j<15

    const int tid  = threadIdx.x;
    const int w    = tid >> 5;               // warp = row 0..15
    const int lane = tid & 31;

    const int b     = blockIdx.x >> 3;       // 16 batches
    const int vbase = (blockIdx.x & 7) << 4; // 8 groups x 16 rows

    const size_t base = (size_t)b * L_SEQ * DK;
    const float* gk = K + base;
    const float* gq = Q + base;
    const float* gv = V + base;
    float*       gy = Y + base;

    // state: lane owns What[w, 4*lane..+3], mhat same
    ull W01 = 0, W23 = 0, M01 = 0, M23 = 0;

    const bool b0 = lane & 1;
    const bool b1 = lane & 2;
    const int  src0 = lane & 28;             // class-0 lane of this 4-group
    // classes 0,1 (k-dots) correct with G; classes 2,3 (q-dots) with H
    const float* corrT = ((lane & 3) < 2) ? Gs : Hs;

    // ---- preload chunk 0 ----
    {
        cp16(su32(&kb[0][0][0]) + tid * 16, gk + tid * 4);
        cp16(su32(&qb[0][0][0]) + tid * 16, gq + tid * 4);
        if (tid < 256) {
            int i = tid >> 4, j = tid & 15;
            cp4(su32(&vT[0][j][i]), gv + (size_t)i * DK + vbase + j);
        }
        cp_commit();
        cp_wait_all();
        __syncthreads();
    }

    for (int chunk = 0; chunk < NCH; ++chunk) {
        const int cur = chunk & 1;
        const int t0  = chunk * CSTEPS;

        // ---- per-chunk prep: warp w computes skq[w], G[w], Hk[w] ----
        {
            const float4 kw = *(const float4*)&kb[cur][w][lane << 2];
            const float4 qw = *(const float4*)&qb[cur][w][lane << 2];
            float p0 = dot4(kw, qw), p1 = 0.0f, p2 = 0.0f;
            if (w < 15) {
                const float4 kw1 = *(const float4*)&kb[cur][w + 1][lane << 2];
                const float4 qw1 = *(const float4*)&qb[cur][w + 1][lane << 2];
                p1 = dot4(kw, kw1);
                p2 = dot4(kw, qw1);
            }
            #pragma unroll
            for (int off = 16; off; off >>= 1) {
                p0 += __shfl_xor_sync(0xffffffffu, p0, off);
                p1 += __shfl_xor_sync(0xffffffffu, p1, off);
                p2 += __shfl_xor_sync(0xffffffffu, p2, off);
            }
            if (lane == 0) {
                skqs[w] = p0;
                if (w < 15) { Gs[w] = p1; Hs[w] = p2; }
            }
        }

        // stage this warp's v row (broadcast LDS.128)
        float vreg[CSTEPS];
        #pragma unroll
        for (int jj = 0; jj < 4; ++jj)
            *(float4*)&vreg[jj * 4] = *(const float4*)&vT[cur][w][jj * 4];

        // prefetch next chunk
        if (chunk + 1 < NCH) {
            const int nb = cur ^ 1;
            const size_t nt = (size_t)(t0 + CSTEPS) * DK;
            cp16(su32(&kb[nb][0][0]) + tid * 16, gk + nt + tid * 4);
            cp16(su32(&qb[nb][0][0]) + tid * 16, gq + nt + tid * 4);
            if (tid < 256) {
                int i = tid >> 4, j = tid & 15;
                cp4(su32(&vT[nb][j][i]), gv + nt + (size_t)i * DK + vbase + j);
            }
        }
        cp_commit();

        __syncthreads();   // skqs/Gs/Hs visible

        // stage kq values (broadcast)
        float skqreg[CSTEPS];
        #pragma unroll
        for (int jj = 0; jj < 4; ++jj)
            *(float4*)&skqreg[jj * 4] = *(const float4*)&skqs[jj * 4];

        // ---- pre-loop: raw dots + fold for step 0 (vs chunk-start state) ----
        float x, t;
        ull kc01, kc23;
        {
            const float4 k4 = *(const float4*)&kb[cur][0][lane << 2];
            const float4 q4 = *(const float4*)&qb[cur][0][lane << 2];
            const ull kn01 = pk(k4.x, k4.y), kn23 = pk(k4.z, k4.w);
            const ull qn01 = pk(q4.x, q4.y), qn23 = pk(q4.z, q4.w);
            float pa = hadd2(fma2(W01, kn01, mul2(W23, kn23)));
            float pb = hadd2(fma2(M01, kn01, mul2(M23, kn23)));
            float pc = hadd2(fma2(W01, qn01, mul2(W23, qn23)));
            float pd = hadd2(fma2(M01, qn01, mul2(M23, qn23)));
            float w1 = b0 ? pa : pb;
            float u  = (b0 ? pb : pa) + __shfl_xor_sync(0xffffffffu, w1, 1);
            float w2 = b0 ? pc : pd;
            float v2 = (b0 ? pd : pc) + __shfl_xor_sync(0xffffffffu, w2, 1);
            float w3 = b1 ? u : v2;
            float xx = (b1 ? v2 : u) + __shfl_xor_sync(0xffffffffu, w3, 2);
            xx += __shfl_xor_sync(0xffffffffu, xx, 4);
            xx += __shfl_xor_sync(0xffffffffu, xx, 8);
            xx += __shfl_xor_sync(0xffffffffu, xx, 16);
            x = xx;
            t = __shfl_xor_sync(0xffffffffu, x, 1);
            kc01 = kn01; kc23 = kn23;
        }

        float rprev = 0.0f;

        // ---- 16 sequential steps ----
        #pragma unroll
        for (int i = 0; i < CSTEPS; ++i) {
            // correction of the pre-state dots using r_{i-1}
            float e1, e2;
            if (i == 0) {
                e1 = x; e2 = t;
            } else {
                const float Vv = corrT[i - 1];        // G or H by class
                const float zc = cA[i - 1] * rprev;
                const float zb = cB[i - 1] * rprev;
                e1 = fmaf(cS[i - 1], t, x);
                e1 = fmaf(zc, Vv, e1);
                e2 = fmaf(zb, Vv, t);
            }
            // r valid in class-0 lanes (e1 = W_i.k_i there); broadcast
            const float rloc = fmaf(cCP[i], e1, -vreg[i]);
            const float r    = __shfl_sync(0xffffffffu, rloc, src0);
            const float ta = cA[i] * r;
            const float tb = cB[i] * r;

            // y from class-2 values (e1 = W_i.q_i, e2 = m_i.q_i there)
            if (lane == 2)
                yb[cur][i][w] = cCY[i] *
                    fmaf(ta, skqreg[i], fmaf(cS[i], e2, e1));

            // raw dots + fold for step i+1 vs PRE-update state (W_i, m_i).
            // Independent of r_i -> overlaps with the scalar chain; the
            // step-i update is accounted for by the correction at i+1.
            float nx = 0.0f, ntv = 0.0f;
            ull kn01 = 0, kn23 = 0;
            if (i + 1 < CSTEPS) {
                const float4 k4 = *(const float4*)&kb[cur][i + 1][lane << 2];
                const float4 q4 = *(const float4*)&qb[cur][i + 1][lane << 2];
                kn01 = pk(k4.x, k4.y); kn23 = pk(k4.z, k4.w);
                const ull qn01 = pk(q4.x, q4.y), qn23 = pk(q4.z, q4.w);
                float pa = hadd2(fma2(W01, kn01, mul2(W23, kn23)));
                float pb = hadd2(fma2(M01, kn01, mul2(M23, kn23)));
                float pc = hadd2(fma2(W01, qn01, mul2(W23, qn23)));
                float pd = hadd2(fma2(M01, qn01, mul2(M23, qn23)));
                float w1 = b0 ? pa : pb;
                float u  = (b0 ? pb : pa) + __shfl_xor_sync(0xffffffffu, w1, 1);
                float w2 = b0 ? pc : pd;
                float v2 = (b0 ? pd : pc) + __shfl_xor_sync(0xffffffffu, w2, 1);
                float w3 = b1 ? u : v2;
                float xx = (b1 ? v2 : u) + __shfl_xor_sync(0xffffffffu, w3, 2);
                xx += __shfl_xor_sync(0xffffffffu, xx, 4);
                xx += __shfl_xor_sync(0xffffffffu, xx, 8);
                xx += __shfl_xor_sync(0xffffffffu, xx, 16);
                nx = xx;
                ntv = __shfl_xor_sync(0xffffffffu, nx, 1);
            }

            // state update for step i (W uses pre-update m), k_i in kc regs
            const ull a2 = pk(ta, ta), b2 = pk(tb, tb), s2 = pk(cS[i], cS[i]);
            W01 = fma2(s2, M01, W01); W01 = fma2(a2, kc01, W01);
            M01 = fma2(b2, kc01, M01);
            W23 = fma2(s2, M23, W23); W23 = fma2(a2, kc23, W23);
            M23 = fma2(b2, kc23, M23);

            rprev = r;
            x = nx; t = ntv;
            kc01 = kn01; kc23 = kn23;
        }

        // chunk-end rescale to fresh frame
        {
            const ull c16 = pk(C16F, C16F);
            const ull b16 = pk(B16F, B16F);
            W01 = mul2(c16, W01); W23 = mul2(c16, W23);
            M01 = mul2(b16, M01); M23 = mul2(b16, M23);
        }

        cp_wait_all();
        __syncthreads();

        // writeback this chunk's y
        if (tid < 256) {
            int i = tid >> 4, j = tid & 15;
            gy[(size_t)(t0 + i) * DK + vbase + j] = yb[cur][i][j];
        }
    }
}

extern "C" void kernel_launch(void* const* d_in, const int* in_sizes, int n_in,
                              void* d_out, int out_size) {
    const float* Q = (const float*)d_in[0];
    const float* K = (const float*)d_in[1];
    const float* V = (const float*)d_in[2];
    float* Y = (float*)d_out;
    (void)in_sizes; (void)n_in; (void)out_size;
    titans_kernel<<<128, 512>>>(Q, K, V, Y);
}